// round 3
// baseline (speedup 1.0000x reference)
#include <cuda_runtime.h>
#include <cuda_bf16.h>
#include <math.h>

// Problem constants (from reference)
//  SRF=3, SRF2=9, ALPHA=2, BETA=8, GAMMA=16, RES=0.5 -> x = d/RES = 2*d
//  log(GAMMA/ALPHA) = log(8)
#define LOG8 2.0794415416798357f

__device__ __forceinline__ float bucket_base(float d) {
    // x = d / 0.5  (exact)
    float x  = d * 2.0f;
    float ax = fabsf(x);
    float r;
    if (ax <= 2.0f) {
        r = rintf(x);                       // jnp.round = half-to-even = rintf
    } else {
        // log_ratio = log(ax/2) / log(8)   (ax > 2 so the max(,1e-6) is moot)
        float lr  = __fdiv_rn(logf(__fmul_rn(ax, 0.5f)), LOG8);
        float sup = fminf(rintf(__fsub_rn(2.0f, __fmul_rn(6.0f, lr))), 8.0f);
        r = (x > 0.0f) ? sup : -sup;        // sign(x) * sup (x != 0 here)
    }
    return 8.0f + r;
}

__global__ __launch_bounds__(256)
void pair_kernel(const float* __restrict__ xyz, const int* __restrict__ grid,
                 float* __restrict__ out, int N) {
    const int i  = blockIdx.y;
    const int j0 = (blockIdx.x * blockDim.x + threadIdx.x) * 4;
    if (j0 >= N) return;

    // ---- per-i data (broadcast across block; cached) ----
    const float xi = __ldg(xyz + (size_t)i * 3 + 0);
    const float yi = __ldg(xyz + (size_t)i * 3 + 1);
    const float zi = __ldg(xyz + (size_t)i * 3 + 2);
    const int bi   = __ldg(grid + (size_t)i * 5 + 0);
    const int bli  = __ldg(grid + (size_t)i * 5 + 1);
    const int ci0  = __ldg(grid + (size_t)i * 5 + 2);
    const int ci1  = __ldg(grid + (size_t)i * 5 + 3);
    const int ci2  = __ldg(grid + (size_t)i * 5 + 4);
    const int cxi  = (int)ceilf(__fdiv_rn(xi, 3.0f));
    const int cyi  = (int)ceilf(__fdiv_rn(yi, 3.0f));
    const int scani = bli >> 1;   // block >= 0

    // ---- 4 j points: vectorized loads ----
    const float4* x4 = reinterpret_cast<const float4*>(xyz + (size_t)j0 * 3);
    float4 f0 = __ldg(x4 + 0), f1 = __ldg(x4 + 1), f2 = __ldg(x4 + 2);
    float xj[4] = {f0.x, f0.w, f1.z, f2.y};
    float yj[4] = {f0.y, f1.x, f1.w, f2.z};
    float zj[4] = {f0.z, f1.y, f2.x, f2.w};

    const int4* g4 = reinterpret_cast<const int4*>(grid + (size_t)j0 * 5);
    int4 r0 = __ldg(g4 + 0), r1 = __ldg(g4 + 1), r2 = __ldg(g4 + 2),
         r3 = __ldg(g4 + 3), r4 = __ldg(g4 + 4);
    // grid row = [batch, block, c0, c1, c2]; 4 rows = 20 ints
    int bj [4] = {r0.x, r1.y, r2.z, r3.w};
    int blj[4] = {r0.y, r1.z, r2.w, r4.x};
    int cj0[4] = {r0.z, r1.w, r3.x, r4.y};
    int cj1[4] = {r0.w, r2.x, r3.y, r4.z};
    int cj2[4] = {r1.x, r2.y, r3.z, r4.w};

    float dxv[12];
    float bkt[4], dsc[4], msk[4];

#pragma unroll
    for (int p = 0; p < 4; p++) {
        float dx = xi - xj[p];
        float dy = yi - yj[p];
        float dz = zi - zj[p];

        bool m = (bi == bj[p]) && (bli <= blj[p]);
        if (m) {
            int ca = max(abs(ci0 - cj0[p]), max(abs(ci1 - cj1[p]), abs(ci2 - cj2[p])));
            bool fk = (bli == blj[p]) && (ca <= 1);
            if (!fk) {
                int cxj = (int)ceilf(__fdiv_rn(xj[p], 3.0f));
                int cyj = (int)ceilf(__fdiv_rn(yj[p], 3.0f));
                bool kc = (abs(cxi - cxj) <= 1) && (abs(cyi - cyj) <= 1);
                // r2 exactly as jnp: round each mul, then sequential adds
                float r2 = __fadd_rn(__fadd_rn(__fmul_rn(dx, dx), __fmul_rn(dy, dy)),
                                     __fmul_rn(dz, dz));
                m = kc && (r2 <= 9.0f);
            }
        }

        if (m) {
            dxv[p * 3 + 0] = dx;
            dxv[p * 3 + 1] = dy;
            dxv[p * 3 + 2] = dz;
            // MUL = [289, 17, 1]; all bucket values are small exact integers in f32
            bkt[p] = __fadd_rn(__fadd_rn(__fmul_rn(289.0f, bucket_base(dx)),
                                         __fmul_rn(17.0f, bucket_base(dy))),
                               bucket_base(dz));
            dsc[p] = (float)((blj[p] >> 1) - scani);   // scanid[j] - scanid[i]
            msk[p] = 1.0f;
        } else {
            dxv[p * 3 + 0] = 0.0f;
            dxv[p * 3 + 1] = 0.0f;
            dxv[p * 3 + 2] = 0.0f;
            bkt[p] = 0.0f;
            dsc[p] = 0.0f;
            msk[p] = 0.0f;
        }
    }

    // ---- vectorized stores (all 16B-aligned) ----
    const size_t NN  = (size_t)N * (size_t)N;
    const size_t row = (size_t)i * N + (size_t)j0;

    float4* dx_out = reinterpret_cast<float4*>(out + row * 3);
    dx_out[0] = make_float4(dxv[0], dxv[1], dxv[2],  dxv[3]);
    dx_out[1] = make_float4(dxv[4], dxv[5], dxv[6],  dxv[7]);
    dx_out[2] = make_float4(dxv[8], dxv[9], dxv[10], dxv[11]);

    *reinterpret_cast<float4*>(out + 3 * NN + row) = make_float4(bkt[0], bkt[1], bkt[2], bkt[3]);
    *reinterpret_cast<float4*>(out + 4 * NN + row) = make_float4(dsc[0], dsc[1], dsc[2], dsc[3]);
    *reinterpret_cast<float4*>(out + 5 * NN + row) = make_float4(msk[0], msk[1], msk[2], msk[3]);
}

extern "C" void kernel_launch(void* const* d_in, const int* in_sizes, int n_in,
                              void* d_out, int out_size) {
    const float* xyz  = (const float*)d_in[0];   // [N,3] f32
    const int*   grid = (const int*)d_in[1];     // [N,5] i32
    float* out = (float*)d_out;                  // [3NN | NN | NN | NN] f32

    const int N = in_sizes[0] / 3;               // 3072

    dim3 block(256, 1, 1);
    dim3 gridDim((N + 256 * 4 - 1) / (256 * 4), N, 1);
    pair_kernel<<<gridDim, block>>>(xyz, grid, out, N);
}